// round 14
// baseline (speedup 1.0000x reference)
#include <cuda_runtime.h>
#include <cuda_bf16.h>
#include <cstdint>
#include <math.h>

#define NN 8192
#define DD 128
#define TILE 128
#define NB (NN / TILE)            // 64
#define NTRI (NB * (NB + 1) / 2)  // 2080 triangular tiles

#define LDT2 144                  // stage row stride bytes (64 bf16 + 16B pad)
#define MAT_BYTES (TILE * LDT2)   // 18432 per matrix per stage
#define STAGE_BYTES (2 * MAT_BYTES) // 36864 (A then B)
#define SMEM_DYN (2 * STAGE_BYTES)  // 73728 -> 2 CTAs/SM (147KB of 227KB)

__device__ double g_sumDW;
__device__ double g_sumW;
__device__ int    g_maxSq;        // float bits; all >= 0 so int-max works
__device__ float  g_norms[NN];
__device__ __nv_bfloat16 g_ehi[NN * DD];

// ---------------- helpers ----------------
__device__ __forceinline__ uint32_t smem_u32(const void* p) {
    uint32_t a;
    asm("{ .reg .u64 t; cvta.to.shared.u64 t, %1; cvt.u32.u64 %0, t; }"
        : "=r"(a) : "l"(p));
    return a;
}
__device__ __forceinline__ void ldsm_x4(uint32_t& r0, uint32_t& r1,
                                        uint32_t& r2, uint32_t& r3, uint32_t a) {
    asm volatile("ldmatrix.sync.aligned.m8n8.x4.shared.b16 {%0,%1,%2,%3}, [%4];"
                 : "=r"(r0), "=r"(r1), "=r"(r2), "=r"(r3) : "r"(a));
}
__device__ __forceinline__ void mma16816(float* d, const uint32_t* a,
                                         const uint32_t* b) {
    asm volatile(
        "mma.sync.aligned.m16n8k16.row.col.f32.bf16.bf16.f32 "
        "{%0,%1,%2,%3}, {%4,%5,%6,%7}, {%8,%9}, {%0,%1,%2,%3};"
        : "+f"(d[0]), "+f"(d[1]), "+f"(d[2]), "+f"(d[3])
        : "r"(a[0]), "r"(a[1]), "r"(a[2]), "r"(a[3]), "r"(b[0]), "r"(b[1]));
}
__device__ __forceinline__ float fsqrt_approx(float x) {
    float r;
    asm("sqrt.approx.f32 %0, %1;" : "=f"(r) : "f"(x));
    return r;
}
__device__ __forceinline__ void cp16(uint32_t dst, const void* src) {
    asm volatile("cp.async.cg.shared.global [%0], [%1], 16;"
                 :: "r"(dst), "l"(src) : "memory");
}
#define CP_COMMIT() asm volatile("cp.async.commit_group;" ::: "memory")

// ---------------- prep kernels ----------------
__global__ void init_kernel() {
    g_sumDW = 0.0;
    g_sumW  = 0.0;
    g_maxSq = 0;
}

__global__ __launch_bounds__(256) void convert_kernel(const float* __restrict__ emb) {
    int idx = blockIdx.x * 256 + threadIdx.x;
    g_ehi[idx] = __float2bfloat16(emb[idx]);
}

__global__ __launch_bounds__(256) void norm_kernel(const float* __restrict__ emb) {
    int row = blockIdx.x * 256 + threadIdx.x;
    const float4* p = reinterpret_cast<const float4*>(emb) + (size_t)row * (DD / 4);
    float s = 0.f;
#pragma unroll
    for (int i = 0; i < DD / 4; i++) {
        float4 v = p[i];
        s += v.x * v.x + v.y * v.y + v.z * v.z + v.w * v.w;
    }
    g_norms[row] = s;
}

// ---------------- main: triangular, 512 threads, 32x32 warp tiles ----------------
__global__ __launch_bounds__(512, 2) void main_kernel(const float* __restrict__ W) {
    extern __shared__ char sm[];
    __shared__ float nI[TILE];
    __shared__ float nJ[TILE];
    __shared__ float redDW[16], redW[16], redM[16];

    const int tid = threadIdx.x;
    const int wid = tid >> 5;     // 0..15
    const int lane = tid & 31;

    // ---- triangular tile decode: bi <= bj ----
    int t = blockIdx.x;
    float ff = 2.0f * NB + 1.0f;
    int bi = (int)((ff - sqrtf(ff * ff - 8.0f * (float)t)) * 0.5f);
    if (bi < 0) bi = 0;
    if (bi > NB - 1) bi = NB - 1;
#define SFUN(b) ((b) * NB - (b) * ((b) - 1) / 2)
    while (bi > 0 && SFUN(bi) > t) bi--;
    while (SFUN(bi + 1) <= t) bi++;
    const int bj = bi + (t - SFUN(bi));
    const int gi0 = bi * TILE;
    const int gj0 = bj * TILE;
    const bool diag = (bi == bj);

    const uint32_t smbase = smem_u32(sm);

    // stage s in {0,1}: K window = s*64 elements
    auto issue_stage = [&](int s) {
        const uint4* src = (const uint4*)g_ehi;
        const int kh = s * 8;                    // uint4 offset within 128-elem row
        const uint32_t buf = smbase + (uint32_t)s * STAGE_BYTES;
#pragma unroll
        for (int it = 0; it < 4; it++) {
            int idx = it * 512 + tid;            // 2048 16B chunks
            int m = idx >> 10;                   // 0 = A, 1 = B
            int r = (idx >> 3) & 127;
            int c = idx & 7;
            const uint4* gsrc = src + (size_t)((m ? gj0 : gi0) + r) * 16 + kh + c;
            cp16(buf + (uint32_t)m * MAT_BYTES + r * LDT2 + c * 16, gsrc);
        }
        CP_COMMIT();
    };

    issue_stage(0);
    issue_stage(1);

    if (tid < TILE)            nI[tid] = g_norms[gi0 + tid];
    else if (tid < 2 * TILE)   nJ[tid - TILE] = g_norms[gj0 + tid - TILE];

    // ---- GEMM: 2 stages of K=64; 16 warps (4x4), 32x32 each ----
    const int wm = wid & 3;
    const int wn = wid >> 2;
    float acc[2][4][4];
#pragma unroll
    for (int mi = 0; mi < 2; mi++)
#pragma unroll
        for (int ni = 0; ni < 4; ni++)
#pragma unroll
            for (int q = 0; q < 4; q++) acc[mi][ni][q] = 0.f;

    const uint32_t a_row = (lane & 15);
    const uint32_t a_koff = ((lane >> 4) << 3) * 2;
    const uint32_t b_row = (lane & 7) + ((lane >> 4) << 3);
    const uint32_t b_koff = (((lane >> 3) & 1) << 3) * 2;

#pragma unroll
    for (int s = 0; s < 2; s++) {
        if (s == 0) asm volatile("cp.async.wait_group 1;" ::: "memory");
        else        asm volatile("cp.async.wait_group 0;" ::: "memory");
        __syncthreads();
        const uint32_t smA = smbase + (uint32_t)s * STAGE_BYTES;
        const uint32_t smB = smA + MAT_BYTES;

#pragma unroll
        for (int ks = 0; ks < 4; ks++) {
            const uint32_t k0b = ks * 32;
            uint32_t af[2][4];
#pragma unroll
            for (int mi = 0; mi < 2; mi++) {
                uint32_t addr = smA + (wm * 32 + mi * 16 + a_row) * LDT2 + k0b + a_koff;
                ldsm_x4(af[mi][0], af[mi][1], af[mi][2], af[mi][3], addr);
            }
            uint32_t bf[4][2];
#pragma unroll
            for (int nq = 0; nq < 2; nq++) {
                uint32_t addr = smB + (wn * 32 + nq * 16 + b_row) * LDT2 + k0b + b_koff;
                uint32_t r0, r1, r2, r3;
                ldsm_x4(r0, r1, r2, r3, addr);
                bf[nq * 2][0] = r0; bf[nq * 2][1] = r1;
                bf[nq * 2 + 1][0] = r2; bf[nq * 2 + 1][1] = r3;
            }
#pragma unroll
            for (int mi = 0; mi < 2; mi++)
#pragma unroll
                for (int ni = 0; ni < 4; ni++)
                    mma16816(acc[mi][ni], af[mi], bf[ni]);
        }
    }

    // ---- register epilogue: dist from acc, W gathered at fragment coords ----
    const int crow = lane >> 2;
    const int ccol = (lane & 3) * 2;
    float sDW = 0.f, sW = 0.f, maxsq = 0.f;

#pragma unroll
    for (int mi = 0; mi < 2; mi++) {
#pragma unroll
        for (int h = 0; h < 2; h++) {
            const int r = wm * 32 + mi * 16 + crow + h * 8;
            const int cbase = wn * 32 + ccol;
            const float* w1row = W + (size_t)(gi0 + r) * NN + gj0 + cbase;
            float2 wv[4];
#pragma unroll
            for (int ni = 0; ni < 4; ni++)
                wv[ni] = *(const float2*)(w1row + ni * 8);     // row-order

            float w2a[4], w2b[4];
            if (!diag) {
                const float* w2col = W + (size_t)gj0 * NN + gi0 + r;
#pragma unroll
                for (int ni = 0; ni < 4; ni++) {               // transposed
                    w2a[ni] = w2col[(size_t)(cbase + ni * 8) * NN];
                    w2b[ni] = w2col[(size_t)(cbase + ni * 8 + 1) * NN];
                }
            }

            const float nival = nI[r];
#pragma unroll
            for (int ni = 0; ni < 4; ni++) {
                float2 nj = *(const float2*)(&nJ[cbase + ni * 8]);
                float s0 = fmaxf(nival + nj.x - 2.f * acc[mi][ni][2 * h],     0.f);
                float s1 = fmaxf(nival + nj.y - 2.f * acc[mi][ni][2 * h + 1], 0.f);
                maxsq = fmaxf(maxsq, fmaxf(s0, s1));
                float d0 = fsqrt_approx(s0);
                float d1 = fsqrt_approx(s1);
                if (diag) {
                    sDW += d0 * wv[ni].x + d1 * wv[ni].y;
                    sW  += wv[ni].x + wv[ni].y;
                } else {
                    sDW += d0 * (wv[ni].x + w2a[ni]) + d1 * (wv[ni].y + w2b[ni]);
                    sW  += (wv[ni].x + w2a[ni]) + (wv[ni].y + w2b[ni]);
                }
            }
        }
    }

    // ---- reductions ----
#pragma unroll
    for (int o = 16; o > 0; o >>= 1) {
        sDW += __shfl_xor_sync(0xFFFFFFFF, sDW, o);
        sW  += __shfl_xor_sync(0xFFFFFFFF, sW, o);
        maxsq = fmaxf(maxsq, __shfl_xor_sync(0xFFFFFFFF, maxsq, o));
    }
    if (lane == 0) { redDW[wid] = sDW; redW[wid] = sW; redM[wid] = maxsq; }
    __syncthreads();
    if (tid == 0) {
        double a = 0.0, b = 0.0;
        float m = 0.f;
#pragma unroll
        for (int w = 0; w < 16; w++) {
            a += (double)redDW[w];
            b += (double)redW[w];
            m = fmaxf(m, redM[w]);
        }
        atomicAdd(&g_sumDW, a);
        atomicAdd(&g_sumW, b);
        atomicMax(&g_maxSq, __float_as_int(m));
    }
}

// ---------------- finalize ----------------
__global__ void finalize_kernel(float* out) {
    double maxd = sqrt((double)__int_as_float(g_maxSq));
    double res = (g_sumW - g_sumDW / maxd) / ((double)NN * (double)NN);
    out[0] = (float)res;
}

extern "C" void kernel_launch(void* const* d_in, const int* in_sizes, int n_in,
                              void* d_out, int out_size) {
    const float* emb = (const float*)d_in[0];   // [8192, 128] fp32
    const float* W   = (const float*)d_in[1];   // [8192, 8192] fp32
    float* out = (float*)d_out;

    cudaFuncSetAttribute(main_kernel, cudaFuncAttributeMaxDynamicSharedMemorySize,
                         SMEM_DYN);

    init_kernel<<<1, 1>>>();
    convert_kernel<<<(NN * DD) / 256, 256>>>(emb);
    norm_kernel<<<NN / 256, 256>>>(emb);
    main_kernel<<<NTRI, 512, SMEM_DYN>>>(W);
    finalize_kernel<<<1, 1>>>(out);
}

// round 15
// speedup vs baseline: 1.0425x; 1.0425x over previous
#include <cuda_runtime.h>
#include <cuda_bf16.h>
#include <cstdint>
#include <math.h>

#define NN 8192
#define DD 128
#define TILE 128
#define NB (NN / TILE)            // 64
#define NTRI (NB * (NB + 1) / 2)  // 2080 triangular tiles
#define NPERS 296                 // persistent CTAs (2 per SM)

#define LDT2 144                  // stage row stride bytes (64 bf16 + 16B pad)
#define MAT_BYTES (TILE * LDT2)   // 18432 per matrix per stage
#define STAGE_BYTES (2 * MAT_BYTES) // 36864 (A then B)
#define SMEM_DYN (2 * STAGE_BYTES)  // 73728 -> 2 CTAs/SM

__device__ double g_sumDW;
__device__ double g_sumW;
__device__ int    g_maxSq;        // float bits; all >= 0 so int-max works
__device__ float  g_norms[NN];
__device__ __nv_bfloat16 g_ehi[NN * DD];

// ---------------- helpers ----------------
__device__ __forceinline__ uint32_t smem_u32(const void* p) {
    uint32_t a;
    asm("{ .reg .u64 t; cvta.to.shared.u64 t, %1; cvt.u32.u64 %0, t; }"
        : "=r"(a) : "l"(p));
    return a;
}
__device__ __forceinline__ void ldsm_x4(uint32_t& r0, uint32_t& r1,
                                        uint32_t& r2, uint32_t& r3, uint32_t a) {
    asm volatile("ldmatrix.sync.aligned.m8n8.x4.shared.b16 {%0,%1,%2,%3}, [%4];"
                 : "=r"(r0), "=r"(r1), "=r"(r2), "=r"(r3) : "r"(a));
}
__device__ __forceinline__ void mma16816(float* d, const uint32_t* a,
                                         const uint32_t* b) {
    asm volatile(
        "mma.sync.aligned.m16n8k16.row.col.f32.bf16.bf16.f32 "
        "{%0,%1,%2,%3}, {%4,%5,%6,%7}, {%8,%9}, {%0,%1,%2,%3};"
        : "+f"(d[0]), "+f"(d[1]), "+f"(d[2]), "+f"(d[3])
        : "r"(a[0]), "r"(a[1]), "r"(a[2]), "r"(a[3]), "r"(b[0]), "r"(b[1]));
}
__device__ __forceinline__ float fsqrt_approx(float x) {
    float r;
    asm("sqrt.approx.f32 %0, %1;" : "=f"(r) : "f"(x));
    return r;
}
__device__ __forceinline__ void cp16(uint32_t dst, const void* src) {
    asm volatile("cp.async.cg.shared.global [%0], [%1], 16;"
                 :: "r"(dst), "l"(src) : "memory");
}
#define CP_COMMIT() asm volatile("cp.async.commit_group;" ::: "memory")
#define CP_WAIT1()  asm volatile("cp.async.wait_group 1;" ::: "memory")

__device__ __forceinline__ void tri_decode(int t, int& bi, int& bj) {
#define SFUN(b) ((b) * NB - (b) * ((b) - 1) / 2)
    float ff = 2.0f * NB + 1.0f;
    int b = (int)((ff - sqrtf(ff * ff - 8.0f * (float)t)) * 0.5f);
    if (b < 0) b = 0;
    if (b > NB - 1) b = NB - 1;
    while (b > 0 && SFUN(b) > t) b--;
    while (SFUN(b + 1) <= t) b++;
    bi = b;
    bj = b + (t - SFUN(b));
}

// ---------------- prep kernels ----------------
__global__ void init_kernel() {
    g_sumDW = 0.0;
    g_sumW  = 0.0;
    g_maxSq = 0;
}

__global__ __launch_bounds__(256) void convert_kernel(const float* __restrict__ emb) {
    int idx = blockIdx.x * 256 + threadIdx.x;
    g_ehi[idx] = __float2bfloat16(emb[idx]);
}

__global__ __launch_bounds__(256) void norm_kernel(const float* __restrict__ emb) {
    int row = blockIdx.x * 256 + threadIdx.x;
    const float4* p = reinterpret_cast<const float4*>(emb) + (size_t)row * (DD / 4);
    float s = 0.f;
#pragma unroll
    for (int i = 0; i < DD / 4; i++) {
        float4 v = p[i];
        s += v.x * v.x + v.y * v.y + v.z * v.z + v.w * v.w;
    }
    g_norms[row] = s;
}

// ---------------- main: persistent, cross-tile pipelined ----------------
__global__ __launch_bounds__(256, 2) void main_kernel(const float* __restrict__ W) {
    extern __shared__ char sm[];
    __shared__ float nI[TILE];
    __shared__ float nJ[TILE];
    __shared__ float redDW[8], redW[8], redM[8];

    const int tid = threadIdx.x;
    const int wid = tid >> 5;
    const int lane = tid & 31;
    const int bid = blockIdx.x;
    const int ntiles = (bid < NTRI) ? ((NTRI - bid - 1) / NPERS + 1) : 0;

    const uint32_t smbase = smem_u32(sm);

    // stage s in {0,1} for tile with row/col gi0/gj0: K window = s*64 elements
    auto issue_stage = [&](int gi0, int gj0, int s) {
        const uint4* src = (const uint4*)g_ehi;
        const int kh = s * 8;                    // uint4 offset within 128-elem row
        const uint32_t buf = smbase + (uint32_t)s * STAGE_BYTES;
#pragma unroll
        for (int it = 0; it < 8; it++) {
            int idx = it * 256 + tid;
            int m = idx >> 10;                   // 0 = A, 1 = B
            int r = (idx >> 3) & 127;
            int c = idx & 7;
            const uint4* gsrc = src + (size_t)((m ? gj0 : gi0) + r) * 16 + kh + c;
            cp16(buf + (uint32_t)m * MAT_BYTES + r * LDT2 + c * 16, gsrc);
        }
        CP_COMMIT();
    };

    const int wm = wid & 3;
    const int wn = wid >> 2;
    const uint32_t a_row = (lane & 15);
    const uint32_t a_koff = ((lane >> 4) << 3) * 2;
    const uint32_t b_row = (lane & 7) + ((lane >> 4) << 3);
    const uint32_t b_koff = (((lane >> 3) & 1) << 3) * 2;
    const int crow = lane >> 2;
    const int ccol = (lane & 3) * 2;

    // cross-tile accumulators (registers; one atomic set at the very end)
    float sDW = 0.f, sW = 0.f, maxsq = 0.f;

    int bi, bj;
    if (ntiles > 0) {
        tri_decode(bid, bi, bj);
        issue_stage(bi * TILE, bj * TILE, 0);
        issue_stage(bi * TILE, bj * TILE, 1);
    }

    for (int k = 0; k < ntiles; k++) {
        const int gi0 = bi * TILE;
        const int gj0 = bj * TILE;
        const bool diag = (bi == bj);

        // next tile coordinates (for prefetch during this tile's epilogue)
        int nbi = 0, nbj = 0;
        const bool have_next = (k + 1 < ntiles);
        if (have_next) tri_decode(bid + NPERS * (k + 1), nbi, nbj);

        __syncthreads();               // prev epilogue's nI/nJ reads complete
        if (tid < TILE) nI[tid] = g_norms[gi0 + tid];
        else            nJ[tid - TILE] = g_norms[gj0 + tid - TILE];

        float acc[2][8][4];
#pragma unroll
        for (int mi = 0; mi < 2; mi++)
#pragma unroll
            for (int ni = 0; ni < 8; ni++)
#pragma unroll
                for (int q = 0; q < 4; q++) acc[mi][ni][q] = 0.f;

        // ---- GEMM: 2 chunks of K=64; stages were prefetched earlier ----
#pragma unroll
        for (int s = 0; s < 2; s++) {
            CP_WAIT1();                // stage s of tile k landed
            __syncthreads();
            const uint32_t smA = smbase + (uint32_t)s * STAGE_BYTES;
            const uint32_t smB = smA + MAT_BYTES;

#pragma unroll
            for (int ks = 0; ks < 4; ks++) {
                const uint32_t k0b = ks * 32;
                uint32_t af[2][4];
#pragma unroll
                for (int mi = 0; mi < 2; mi++) {
                    uint32_t addr = smA + (wm * 32 + mi * 16 + a_row) * LDT2 + k0b + a_koff;
                    ldsm_x4(af[mi][0], af[mi][1], af[mi][2], af[mi][3], addr);
                }
                uint32_t bf[8][2];
#pragma unroll
                for (int nq = 0; nq < 4; nq++) {
                    uint32_t addr = smB + (wn * 64 + nq * 16 + b_row) * LDT2 + k0b + b_koff;
                    uint32_t r0, r1, r2, r3;
                    ldsm_x4(r0, r1, r2, r3, addr);
                    bf[nq * 2][0] = r0; bf[nq * 2][1] = r1;
                    bf[nq * 2 + 1][0] = r2; bf[nq * 2 + 1][1] = r3;
                }
#pragma unroll
                for (int mi = 0; mi < 2; mi++)
#pragma unroll
                    for (int ni = 0; ni < 8; ni++)
                        mma16816(acc[mi][ni], af[mi], bf[ni]);
            }
            __syncthreads();           // buffer s fully consumed
            if (have_next) issue_stage(nbi * TILE, nbj * TILE, s);  // prefetch next tile
        }

        // ---- register epilogue (next tile's stages streaming underneath) ----
#pragma unroll
        for (int mi = 0; mi < 2; mi++) {
#pragma unroll
            for (int h = 0; h < 2; h++) {
                const int r = wm * 32 + mi * 16 + crow + h * 8;
                const int cbase = wn * 64 + ccol;
                const float* w1row = W + (size_t)(gi0 + r) * NN + gj0 + cbase;
                float2 wv[8];
#pragma unroll
                for (int ni = 0; ni < 8; ni++)
                    wv[ni] = *(const float2*)(w1row + ni * 8);     // row-order, MLP-8

                float w2a[8], w2b[8];
                if (!diag) {
                    const float* w2col = W + (size_t)gj0 * NN + gi0 + r;
#pragma unroll
                    for (int ni = 0; ni < 8; ni++) {               // transposed, MLP-16
                        w2a[ni] = w2col[(size_t)(cbase + ni * 8) * NN];
                        w2b[ni] = w2col[(size_t)(cbase + ni * 8 + 1) * NN];
                    }
                }

                const float nival = nI[r];
#pragma unroll
                for (int ni = 0; ni < 8; ni++) {
                    float2 nj = *(const float2*)(&nJ[cbase + ni * 8]);
                    float s0 = fmaxf(nival + nj.x - 2.f * acc[mi][ni][2 * h],     0.f);
                    float s1 = fmaxf(nival + nj.y - 2.f * acc[mi][ni][2 * h + 1], 0.f);
                    maxsq = fmaxf(maxsq, fmaxf(s0, s1));
                    float d0 = fsqrt_approx(s0);
                    float d1 = fsqrt_approx(s1);
                    if (diag) {
                        sDW += d0 * wv[ni].x + d1 * wv[ni].y;
                        sW  += wv[ni].x + wv[ni].y;
                    } else {
                        sDW += d0 * (wv[ni].x + w2a[ni]) + d1 * (wv[ni].y + w2b[ni]);
                        sW  += (wv[ni].x + w2a[ni]) + (wv[ni].y + w2b[ni]);
                    }
                }
            }
        }

        bi = nbi; bj = nbj;
    }

    // ---- final reductions (once per CTA) ----
#pragma unroll
    for (int o = 16; o > 0; o >>= 1) {
        sDW += __shfl_xor_sync(0xFFFFFFFF, sDW, o);
        sW  += __shfl_xor_sync(0xFFFFFFFF, sW, o);
        maxsq = fmaxf(maxsq, __shfl_xor_sync(0xFFFFFFFF, maxsq, o));
    }
    __syncthreads();
    if (lane == 0) { redDW[wid] = sDW; redW[wid] = sW; redM[wid] = maxsq; }
    __syncthreads();
    if (tid == 0) {
        double a = 0.0, b = 0.0;
        float m = 0.f;
#pragma unroll
        for (int w = 0; w < 8; w++) {
            a += (double)redDW[w];
            b += (double)redW[w];
            m = fmaxf(m, redM[w]);
        }
        atomicAdd(&g_sumDW, a);
        atomicAdd(&g_sumW, b);
        atomicMax(&g_maxSq, __float_as_int(m));
    }
}

// ---------------- finalize ----------------
__global__ void finalize_kernel(float* out) {
    double maxd = sqrt((double)__int_as_float(g_maxSq));
    double res = (g_sumW - g_sumDW / maxd) / ((double)NN * (double)NN);
    out[0] = (float)res;
}

extern "C" void kernel_launch(void* const* d_in, const int* in_sizes, int n_in,
                              void* d_out, int out_size) {
    const float* emb = (const float*)d_in[0];   // [8192, 128] fp32
    const float* W   = (const float*)d_in[1];   // [8192, 8192] fp32
    float* out = (float*)d_out;

    cudaFuncSetAttribute(main_kernel, cudaFuncAttributeMaxDynamicSharedMemorySize,
                         SMEM_DYN);

    init_kernel<<<1, 1>>>();
    convert_kernel<<<(NN * DD) / 256, 256>>>(emb);
    norm_kernel<<<NN / 256, 256>>>(emb);
    main_kernel<<<NPERS, 256, SMEM_DYN>>>(W);
    finalize_kernel<<<1, 1>>>(out);
}

// round 16
// speedup vs baseline: 1.0930x; 1.0484x over previous
#include <cuda_runtime.h>
#include <cuda_bf16.h>
#include <cstdint>
#include <math.h>

#define NN 8192
#define DD 128
#define TILE 128
#define NB (NN / TILE)            // 64
#define NTRI (NB * (NB + 1) / 2)  // 2080 triangular tiles
#define NPERS 296                 // persistent CTAs (2 per SM)

#define LDT2 144                  // row stride bytes (64 bf16 + 16B pad)
#define HALF_BYTES (TILE * LDT2)  // 18432 per K=64 half
#define OFF_A 0                   // A: both K-halves, 36864 B
#define OFF_B (2 * HALF_BYTES)    // B: 2 pipeline slots (one K-half each)
#define SMEM_DYN (4 * HALF_BYTES) // 73728 -> 2 CTAs/SM

__device__ double g_sumDW;
__device__ double g_sumW;
__device__ int    g_maxSq;        // float bits; all >= 0 so int-max works
__device__ float  g_norms[NN];
__device__ __nv_bfloat162 g_ehi2[NN * DD / 2];

// ---------------- helpers ----------------
__device__ __forceinline__ uint32_t smem_u32(const void* p) {
    uint32_t a;
    asm("{ .reg .u64 t; cvta.to.shared.u64 t, %1; cvt.u32.u64 %0, t; }"
        : "=r"(a) : "l"(p));
    return a;
}
__device__ __forceinline__ void ldsm_x4(uint32_t& r0, uint32_t& r1,
                                        uint32_t& r2, uint32_t& r3, uint32_t a) {
    asm volatile("ldmatrix.sync.aligned.m8n8.x4.shared.b16 {%0,%1,%2,%3}, [%4];"
                 : "=r"(r0), "=r"(r1), "=r"(r2), "=r"(r3) : "r"(a));
}
__device__ __forceinline__ void mma16816(float* d, const uint32_t* a,
                                         const uint32_t* b) {
    asm volatile(
        "mma.sync.aligned.m16n8k16.row.col.f32.bf16.bf16.f32 "
        "{%0,%1,%2,%3}, {%4,%5,%6,%7}, {%8,%9}, {%0,%1,%2,%3};"
        : "+f"(d[0]), "+f"(d[1]), "+f"(d[2]), "+f"(d[3])
        : "r"(a[0]), "r"(a[1]), "r"(a[2]), "r"(a[3]), "r"(b[0]), "r"(b[1]));
}
__device__ __forceinline__ float fsqrt_approx(float x) {
    float r;
    asm("sqrt.approx.f32 %0, %1;" : "=f"(r) : "f"(x));
    return r;
}
__device__ __forceinline__ void cp16(uint32_t dst, const void* src) {
    asm volatile("cp.async.cg.shared.global [%0], [%1], 16;"
                 :: "r"(dst), "l"(src) : "memory");
}
#define CP_COMMIT() asm volatile("cp.async.commit_group;" ::: "memory")
#define CP_WAIT1()  asm volatile("cp.async.wait_group 1;" ::: "memory")

// ---------------- fused prep: init + bf16 convert + row norms ----------------
__global__ __launch_bounds__(256) void prep_kernel(const float* __restrict__ emb) {
    const int tid = threadIdx.x;
    const int wid = tid >> 5;
    const int lane = tid & 31;
    const int row = blockIdx.x * 8 + wid;

    if (blockIdx.x == 0 && tid == 0) {
        g_sumDW = 0.0;
        g_sumW  = 0.0;
        g_maxSq = 0;
    }

    // warp per row: lane handles floats [lane*4, lane*4+4)
    float4 v = reinterpret_cast<const float4*>(emb)[(size_t)row * 32 + lane];
    __nv_bfloat162 b01 = __floats2bfloat162_rn(v.x, v.y);
    __nv_bfloat162 b23 = __floats2bfloat162_rn(v.z, v.w);
    g_ehi2[(size_t)row * 64 + lane * 2]     = b01;
    g_ehi2[(size_t)row * 64 + lane * 2 + 1] = b23;

    float s = v.x * v.x + v.y * v.y + v.z * v.z + v.w * v.w;
#pragma unroll
    for (int o = 16; o > 0; o >>= 1) s += __shfl_xor_sync(0xFFFFFFFF, s, o);
    if (lane == 0) g_norms[row] = s;
}

// ---------------- main: persistent, contiguous ranges, A-tile reuse ----------------
__global__ __launch_bounds__(256, 2) void main_kernel(const float* __restrict__ W) {
    extern __shared__ char sm[];
    __shared__ float nI[TILE];
    __shared__ float nJ[TILE];
    __shared__ float redDW[8], redW[8], redM[8];

    const int tid = threadIdx.x;
    const int wid = tid >> 5;
    const int lane = tid & 31;
    const int bid = blockIdx.x;

    // contiguous range [start, end)
    const int start = (int)(((long long)bid * NTRI) / NPERS);
    const int end   = (int)(((long long)(bid + 1) * NTRI) / NPERS);
    const int ntiles = end - start;

    const uint32_t smbase = smem_u32(sm);
    const uint4* src = (const uint4*)g_ehi2;

    // B K-half s of tile (gj0) into pipeline slot s
    auto issue_stageB = [&](int gj0, int s) {
#pragma unroll
        for (int it = 0; it < 4; it++) {
            int idx = it * 256 + tid;            // 1024 16B chunks
            int r = idx >> 3, c = idx & 7;
            cp16(smbase + OFF_B + (uint32_t)s * HALF_BYTES + r * LDT2 + c * 16,
                 src + (size_t)(gj0 + r) * 16 + s * 8 + c);
        }
        CP_COMMIT();
    };
    // A tile (both halves), plain LDG->STS; rare (bi change only)
    auto load_A = [&](int gi0) {
#pragma unroll
        for (int it = 0; it < 8; it++) {
            int idx = it * 256 + tid;            // 2048 16B chunks
            int half = idx >> 10;
            int r = (idx >> 3) & 127;
            int c = idx & 7;
            *(uint4*)(sm + OFF_A + half * HALF_BYTES + r * LDT2 + c * 16) =
                src[(size_t)(gi0 + r) * 16 + half * 8 + c];
        }
    };

    // triangular decode of 'start' only; then increment
    int bi, bj;
    {
#define SFUN(b) ((b) * NB - (b) * ((b) - 1) / 2)
        float ff = 2.0f * NB + 1.0f;
        int b = (int)((ff - sqrtf(ff * ff - 8.0f * (float)start)) * 0.5f);
        if (b < 0) b = 0;
        if (b > NB - 1) b = NB - 1;
        while (b > 0 && SFUN(b) > start) b--;
        while (SFUN(b + 1) <= start) b++;
        bi = b;
        bj = b + (start - SFUN(b));
    }

    const int wm = wid & 3;
    const int wn = wid >> 2;
    const uint32_t a_row = (lane & 15);
    const uint32_t a_koff = ((lane >> 4) << 3) * 2;
    const uint32_t b_row = (lane & 7) + ((lane >> 4) << 3);
    const uint32_t b_koff = (((lane >> 3) & 1) << 3) * 2;
    const int crow = lane >> 2;
    const int ccol = (lane & 3) * 2;

    float sDW = 0.f, sW = 0.f, maxsq = 0.f;
    int cur_bi = -1;

    if (ntiles > 0) {
        issue_stageB(bj * TILE, 0);
        issue_stageB(bj * TILE, 1);
    }

    for (int k = 0; k < ntiles; k++) {
        const int gi0 = bi * TILE;
        const int gj0 = bj * TILE;
        const bool diag = (bi == bj);

        // next tile coords (contiguous order)
        int nbi = bi, nbj = bj + 1;
        if (nbj == NB) { nbi = bi + 1; nbj = nbi; }
        const bool have_next = (k + 1 < ntiles);

        __syncthreads();               // prev epilogue's nI/nJ & prev-tile A reads done
        if (bi != cur_bi) {            // reload A tile + nI (rare)
            load_A(gi0);
            cur_bi = bi;
        }
        if (tid < TILE) nI[tid] = g_norms[gi0 + tid];
        else            nJ[tid - TILE] = g_norms[gj0 + tid - TILE];

        float acc[2][8][4];
#pragma unroll
        for (int mi = 0; mi < 2; mi++)
#pragma unroll
            for (int ni = 0; ni < 8; ni++)
#pragma unroll
                for (int q = 0; q < 4; q++) acc[mi][ni][q] = 0.f;

        // ---- GEMM: 2 K-halves; A resident, B pipelined ----
#pragma unroll
        for (int s = 0; s < 2; s++) {
            CP_WAIT1();                // B half s of this tile landed
            __syncthreads();
            const uint32_t smA = smbase + OFF_A + (uint32_t)s * HALF_BYTES;
            const uint32_t smB = smbase + OFF_B + (uint32_t)s * HALF_BYTES;

#pragma unroll
            for (int ks = 0; ks < 4; ks++) {
                const uint32_t k0b = ks * 32;
                uint32_t af[2][4];
#pragma unroll
                for (int mi = 0; mi < 2; mi++) {
                    uint32_t addr = smA + (wm * 32 + mi * 16 + a_row) * LDT2 + k0b + a_koff;
                    ldsm_x4(af[mi][0], af[mi][1], af[mi][2], af[mi][3], addr);
                }
                uint32_t bf[8][2];
#pragma unroll
                for (int nq = 0; nq < 4; nq++) {
                    uint32_t addr = smB + (wn * 64 + nq * 16 + b_row) * LDT2 + k0b + b_koff;
                    uint32_t r0, r1, r2, r3;
                    ldsm_x4(r0, r1, r2, r3, addr);
                    bf[nq * 2][0] = r0; bf[nq * 2][1] = r1;
                    bf[nq * 2 + 1][0] = r2; bf[nq * 2 + 1][1] = r3;
                }
#pragma unroll
                for (int mi = 0; mi < 2; mi++)
#pragma unroll
                    for (int ni = 0; ni < 8; ni++)
                        mma16816(acc[mi][ni], af[mi], bf[ni]);
            }
            __syncthreads();           // B slot s fully consumed
            if (have_next) issue_stageB(nbj * TILE, s);   // prefetch next tile's half s
        }

        // ---- register epilogue ----
#pragma unroll
        for (int mi = 0; mi < 2; mi++) {
#pragma unroll
            for (int h = 0; h < 2; h++) {
                const int r = wm * 32 + mi * 16 + crow + h * 8;
                const int cbase = wn * 64 + ccol;
                const float* w1row = W + (size_t)(gi0 + r) * NN + gj0 + cbase;
                float2 wv[8];
#pragma unroll
                for (int ni = 0; ni < 8; ni++)
                    wv[ni] = *(const float2*)(w1row + ni * 8);     // row-order, MLP-8

                float w2a[8], w2b[8];
                if (!diag) {
                    const float* w2col = W + (size_t)gj0 * NN + gi0 + r;
#pragma unroll
                    for (int ni = 0; ni < 8; ni++) {               // transposed, MLP-16
                        w2a[ni] = w2col[(size_t)(cbase + ni * 8) * NN];
                        w2b[ni] = w2col[(size_t)(cbase + ni * 8 + 1) * NN];
                    }
                }

                const float nival = nI[r];
#pragma unroll
                for (int ni = 0; ni < 8; ni++) {
                    float2 nj = *(const float2*)(&nJ[cbase + ni * 8]);
                    float s0 = fmaxf(nival + nj.x - 2.f * acc[mi][ni][2 * h],     0.f);
                    float s1 = fmaxf(nival + nj.y - 2.f * acc[mi][ni][2 * h + 1], 0.f);
                    maxsq = fmaxf(maxsq, fmaxf(s0, s1));
                    float d0 = fsqrt_approx(s0);
                    float d1 = fsqrt_approx(s1);
                    if (diag) {
                        sDW += d0 * wv[ni].x + d1 * wv[ni].y;
                        sW  += wv[ni].x + wv[ni].y;
                    } else {
                        sDW += d0 * (wv[ni].x + w2a[ni]) + d1 * (wv[ni].y + w2b[ni]);
                        sW  += (wv[ni].x + w2a[ni]) + (wv[ni].y + w2b[ni]);
                    }
                }
            }
        }

        bi = nbi; bj = nbj;
    }

    // ---- final reductions (once per CTA) ----
#pragma unroll
    for (int o = 16; o > 0; o >>= 1) {
        sDW += __shfl_xor_sync(0xFFFFFFFF, sDW, o);
        sW  += __shfl_xor_sync(0xFFFFFFFF, sW, o);
        maxsq = fmaxf(maxsq, __shfl_xor_sync(0xFFFFFFFF, maxsq, o));
    }
    __syncthreads();
    if (lane == 0) { redDW[wid] = sDW; redW[wid] = sW; redM[wid] = maxsq; }
    __syncthreads();
    if (tid == 0) {
        double a = 0.0, b = 0.0;
        float m = 0.f;
#pragma unroll
        for (int w = 0; w < 8; w++) {
            a += (double)redDW[w];
            b += (double)redW[w];
            m = fmaxf(m, redM[w]);
        }
        atomicAdd(&g_sumDW, a);
        atomicAdd(&g_sumW, b);
        atomicMax(&g_maxSq, __float_as_int(m));
    }
}

// ---------------- finalize ----------------
__global__ void finalize_kernel(float* out) {
    double maxd = sqrt((double)__int_as_float(g_maxSq));
    double res = (g_sumW - g_sumDW / maxd) / ((double)NN * (double)NN);
    out[0] = (float)res;
}

extern "C" void kernel_launch(void* const* d_in, const int* in_sizes, int n_in,
                              void* d_out, int out_size) {
    const float* emb = (const float*)d_in[0];   // [8192, 128] fp32
    const float* W   = (const float*)d_in[1];   // [8192, 8192] fp32
    float* out = (float*)d_out;

    cudaFuncSetAttribute(main_kernel, cudaFuncAttributeMaxDynamicSharedMemorySize,
                         SMEM_DYN);

    prep_kernel<<<NN / 8, 256>>>(emb);
    main_kernel<<<NPERS, 256, SMEM_DYN>>>(W);
    finalize_kernel<<<1, 1>>>(out);
}